// round 2
// baseline (speedup 1.0000x reference)
#include <cuda_runtime.h>
#include <stdint.h>

// YOLO loss, single fused kernel.
// Inputs: pred (N,28,28,30) f32, target_boxes (N,28,28,4) f32,
// target_cls (N,28,28,20) f32, has_object_map (N,28,28) bool (dtype auto-detected
// per-block from byte patterns). Output: 5 f32 [total, reg, contain, noobj, cls]/N.

#define SGRID 28
#define TPB   128
#define CELLS 128
#define MAXBLK 8192
#define L_COORD 5.0
#define L_NOOBJ 0.5

__device__ float4        g_part[MAXBLK];
__device__ unsigned int  g_count = 0;

__device__ __forceinline__ float iou_vs_t(float b0c, float b1c, float bw, float bh,
                                          float t0, float t1, float t2, float t3) {
    const float invS = 1.0f / (float)SGRID;
    float bx = b0c * invS, by = b1c * invS;
    float b0 = bx - 0.5f * bw, b1 = by - 0.5f * bh;
    float b2 = bx + 0.5f * bw, b3 = by + 0.5f * bh;
    float lt0 = fmaxf(b0, t0), lt1 = fmaxf(b1, t1);
    float rb0 = fminf(b2, t2), rb1 = fminf(b3, t3);
    float w = fmaxf(rb0 - lt0, 0.0f), h = fmaxf(rb1 - lt1, 0.0f);
    float inter = w * h;
    float a1 = (b2 - b0) * (b3 - b1);
    float a2 = (t2 - t0) * (t3 - t1);
    float denom = a1 + a2 - inter;
    return inter / (denom > 0.0f ? denom : 1.0f);
}

__global__ void __launch_bounds__(TPB)
yolo_fused(const float* __restrict__ pred,
           const float* __restrict__ tbox,
           const float* __restrict__ tcls,
           const void*  __restrict__ mask,
           int ncells, int nblocks,
           float* __restrict__ out, double invN) {
    __shared__ float  s_pred[CELLS * 31];   // padded 30->31: conflict-free gather
    __shared__ float  s_tcls[CELLS * 21];   // padded 20->21
    __shared__ float4 s_tbox[CELLS];
    __shared__ int    s_gt1, s_off, s_last;
    __shared__ float4 s_red[TPB / 32];
    __shared__ double s_dred[TPB / 32][4];

    const int tid  = threadIdx.x;
    const int bid  = blockIdx.x;
    const int base = bid * CELLS;
    const int bcnt = min(CELLS, ncells - base);   // cells in this block
    const bool full = (bcnt == CELLS);

    if (tid == 0) { s_gt1 = 0; s_off = 0; s_last = 0; }
    __syncthreads();

    // ---- mask dtype detection: scan first 2KB (L2-hot after first block) ----
    // f32 1.0 has bytes >1 (0x80,0x3f). int32 0/1 has nonzero only at i%4==0.
    // 4-byte element <=> (any byte>1) || (no nonzero at i%4!=0).
    {
        const unsigned char* m = (const unsigned char*)mask;
        int lim = min(2048, ncells);    // >=1 byte per cell in every mode
        int lgt1 = 0, loff = 0;
        for (int i = tid * 16; i < lim; i += TPB * 16) {
            #pragma unroll
            for (int k = 0; k < 16; k++) {
                if (i + k < lim) {
                    unsigned char b = m[i + k];
                    if (b > 1) lgt1 = 1;
                    if (((i + k) & 3) != 0 && b != 0) loff = 1;
                }
            }
        }
        if (__any_sync(0xFFFFFFFFu, lgt1) && (tid & 31) == 0) atomicOr(&s_gt1, 1);
        if (__any_sync(0xFFFFFFFFu, loff) && (tid & 31) == 0) atomicOr(&s_off, 1);
    }

    // ---- coalesced staging: gmem float4 -> padded smem ----
    if (full) {
        const float4* g4 = (const float4*)(pred + (size_t)base * 30);
        #pragma unroll 4
        for (int i = tid; i < CELLS * 30 / 4; i += TPB) {   // 960 float4
            float4 v = g4[i];
            int e = i * 4;
            s_pred[(e / 30) * 31 + (e % 30)] = v.x; e++;
            s_pred[(e / 30) * 31 + (e % 30)] = v.y; e++;
            s_pred[(e / 30) * 31 + (e % 30)] = v.z; e++;
            s_pred[(e / 30) * 31 + (e % 30)] = v.w;
        }
        const float4* c4 = (const float4*)(tcls + (size_t)base * 20);
        #pragma unroll 4
        for (int i = tid; i < CELLS * 20 / 4; i += TPB) {   // 640 float4
            float4 v = c4[i];
            int e = i * 4;
            s_tcls[(e / 20) * 21 + (e % 20)] = v.x; e++;
            s_tcls[(e / 20) * 21 + (e % 20)] = v.y; e++;
            s_tcls[(e / 20) * 21 + (e % 20)] = v.z; e++;
            s_tcls[(e / 20) * 21 + (e % 20)] = v.w;
        }
        s_tbox[tid] = ((const float4*)tbox)[base + tid];
    } else {
        for (int e = tid; e < bcnt * 30; e += TPB)
            s_pred[(e / 30) * 31 + (e % 30)] = pred[(size_t)base * 30 + e];
        for (int e = tid; e < bcnt * 20; e += TPB)
            s_tcls[(e / 20) * 21 + (e % 20)] = tcls[(size_t)base * 20 + e];
        if (tid < bcnt) s_tbox[tid] = ((const float4*)tbox)[base + tid];
    }
    __syncthreads();

    const bool four_byte = (s_gt1 != 0) || (s_off == 0);

    // ---- per-cell loss ----
    float scls = 0.0f, sno = 0.0f, sreg = 0.0f, sct = 0.0f;
    if (tid < bcnt) {
        const int c = base + tid;
        float fm;
        if (four_byte) fm = (((const unsigned int*)mask)[c] != 0u) ? 1.0f : 0.0f;
        else           fm = (((const unsigned char*)mask)[c] != 0)  ? 1.0f : 0.0f;

        const float* P = s_pred + tid * 31;
        const float* C = s_tcls + tid * 21;
        float4 tb = s_tbox[tid];

        float cls = 0.0f;
        #pragma unroll
        for (int j = 0; j < 20; j++) {
            float d = P[10 + j] - C[j];
            cls = fmaf(d, d, cls);
        }
        scls = fm * cls;

        sno = (1.0f - fm) * (P[4] * P[4] + P[9] * P[9]);   // raw; x0.5 later

        const float invS = 1.0f / (float)SGRID;
        float tx = tb.x * invS, ty = tb.y * invS;
        float t0 = tx - 0.5f * tb.z, t1 = ty - 0.5f * tb.w;
        float t2 = tx + 0.5f * tb.z, t3 = ty + 0.5f * tb.w;

        float i1 = iou_vs_t(P[0], P[1], P[2], P[3], t0, t1, t2, t3);
        float i2 = iou_vs_t(P[5], P[6], P[7], P[8], t0, t1, t2, t3);
        bool take1 = i1 > i2;
        float bx0 = take1 ? P[0] : P[5];
        float bx1 = take1 ? P[1] : P[6];
        float bx2 = take1 ? P[2] : P[7];
        float bx3 = take1 ? P[3] : P[8];
        float bx4 = take1 ? P[4] : P[9];
        float best_iou = take1 ? i1 : i2;

        float dx = bx0 - tb.x, dy = bx1 - tb.y;
        float xy = dx * dx + dy * dy;

        bool on = fm > 0.0f;
        float dw = sqrtf(on ? bx2 : 1.0f) - sqrtf(on ? tb.z : 1.0f);
        float dh = sqrtf(on ? bx3 : 1.0f) - sqrtf(on ? tb.w : 1.0f);
        sreg = fm * (xy + dw * dw + dh * dh);              // raw; x5 later

        float dc = bx4 - best_iou;
        sct = fm * dc * dc;
    }

    // ---- block reduce (fp32) ----
    #pragma unroll
    for (int off = 16; off > 0; off >>= 1) {
        scls += __shfl_down_sync(0xFFFFFFFFu, scls, off);
        sno  += __shfl_down_sync(0xFFFFFFFFu, sno,  off);
        sreg += __shfl_down_sync(0xFFFFFFFFu, sreg, off);
        sct  += __shfl_down_sync(0xFFFFFFFFu, sct,  off);
    }
    int wid = tid >> 5, lid = tid & 31;
    if (lid == 0) s_red[wid] = make_float4(scls, sno, sreg, sct);
    __syncthreads();
    if (tid == 0) {
        float4 v = s_red[0];
        #pragma unroll
        for (int w = 1; w < TPB / 32; w++) {
            v.x += s_red[w].x; v.y += s_red[w].y;
            v.z += s_red[w].z; v.w += s_red[w].w;
        }
        g_part[bid] = v;
        __threadfence();
        unsigned int done = atomicAdd(&g_count, 1u);
        if (done == (unsigned int)nblocks - 1u) s_last = 1;
    }
    __syncthreads();

    // ---- last block finalizes ----
    if (s_last) {
        double dx = 0.0, dy = 0.0, dz = 0.0, dw = 0.0;
        for (int i = tid; i < nblocks; i += TPB) {
            float4 v = g_part[i];
            dx += (double)v.x; dy += (double)v.y;
            dz += (double)v.z; dw += (double)v.w;
        }
        #pragma unroll
        for (int off = 16; off > 0; off >>= 1) {
            dx += __shfl_down_sync(0xFFFFFFFFu, dx, off);
            dy += __shfl_down_sync(0xFFFFFFFFu, dy, off);
            dz += __shfl_down_sync(0xFFFFFFFFu, dz, off);
            dw += __shfl_down_sync(0xFFFFFFFFu, dw, off);
        }
        if (lid == 0) {
            s_dred[wid][0] = dx; s_dred[wid][1] = dy;
            s_dred[wid][2] = dz; s_dred[wid][3] = dw;
        }
        __syncthreads();
        if (tid == 0) {
            double cls = 0.0, no = 0.0, reg = 0.0, ct = 0.0;
            #pragma unroll
            for (int w = 0; w < TPB / 32; w++) {
                cls += s_dred[w][0]; no += s_dred[w][1];
                reg += s_dred[w][2]; ct += s_dred[w][3];
            }
            no  *= L_NOOBJ;
            reg *= L_COORD;
            double tot = cls + no + reg + ct;
            out[0] = (float)(tot * invN);
            out[1] = (float)(reg * invN);
            out[2] = (float)(ct  * invN);
            out[3] = (float)(no  * invN);
            out[4] = (float)(cls * invN);
            g_count = 0;   // reset for next graph replay
        }
    }
}

extern "C" void kernel_launch(void* const* d_in, const int* in_sizes, int n_in,
                              void* d_out, int out_size) {
    const float* pred = (const float*)d_in[0];
    const float* tbox = (const float*)d_in[1];
    const float* tcls = (const float*)d_in[2];
    const void*  mask = d_in[3];

    int ncells = in_sizes[0] / 30;               // N*28*28
    int nbatch = ncells / (SGRID * SGRID);       // N
    double invN = 1.0 / (double)nbatch;
    int nblocks = (ncells + CELLS - 1) / CELLS;  // 6272 for N=1024

    yolo_fused<<<nblocks, TPB>>>(pred, tbox, tcls, mask, ncells, nblocks,
                                 (float*)d_out, invN);
}

// round 3
// speedup vs baseline: 1.1558x; 1.1558x over previous
#include <cuda_runtime.h>
#include <stdint.h>

// YOLO loss, single fused kernel, ALU-free coalesced smem staging.
// Inputs: pred (N,28,28,30) f32, target_boxes (N,28,28,4) f32,
// target_cls (N,28,28,20) f32, has_object_map (N,28,28) bool (dtype auto-detect).
// Output: 5 f32 [total, reg, contain, noobj, cls] / N.

#define SGRID 28
#define TPB   128
#define CELLS 128
#define MAXBLK 16384
#define L_COORD 5.0
#define L_NOOBJ 0.5

__device__ float4       g_part[MAXBLK];
__device__ unsigned int g_count = 0;

__device__ __forceinline__ float iou_vs_t(float bcx, float bcy, float bw, float bh,
                                          float t0, float t1, float t2, float t3) {
    const float invS = 1.0f / (float)SGRID;
    float bx = bcx * invS, by = bcy * invS;
    float b0 = bx - 0.5f * bw, b1 = by - 0.5f * bh;
    float b2 = bx + 0.5f * bw, b3 = by + 0.5f * bh;
    float lt0 = fmaxf(b0, t0), lt1 = fmaxf(b1, t1);
    float rb0 = fminf(b2, t2), rb1 = fminf(b3, t3);
    float w = fmaxf(rb0 - lt0, 0.0f), h = fmaxf(rb1 - lt1, 0.0f);
    float inter = w * h;
    float a1 = (b2 - b0) * (b3 - b1);
    float a2 = (t2 - t0) * (t3 - t1);
    float denom = a1 + a2 - inter;
    return inter / (denom > 0.0f ? denom : 1.0f);
}

__global__ void __launch_bounds__(TPB)
yolo_fused(const float* __restrict__ pred,
           const float* __restrict__ tbox,
           const float* __restrict__ tcls,
           const void*  __restrict__ mask,
           int ncells, int nblocks,
           float* __restrict__ out, double invN) {
    __shared__ float4 s_pred4[CELLS * 30 / 4];   // 960: linear, no remap
    __shared__ float4 s_tcls4[CELLS * 20 / 4];   // 640: linear, no remap
    __shared__ float4 s_tbox[CELLS];
    __shared__ int    s_last;
    __shared__ float4 s_red[TPB / 32];
    __shared__ double s_dred[TPB / 32][4];

    const int tid  = threadIdx.x;
    const int bid  = blockIdx.x;
    const int base = bid * CELLS;
    const int bcnt = min(CELLS, ncells - base);
    const bool full = (bcnt == CELLS);

    if (tid == 0) s_last = 0;

    // ---- coalesced staging: gmem float4 -> smem float4, identity mapping ----
    if (full) {
        const float4* p4 = (const float4*)(pred + (size_t)base * 30);
        #pragma unroll
        for (int k = 0; k < 7; k++)                       // 7*128 = 896
            s_pred4[tid + k * TPB] = p4[tid + k * TPB];
        if (tid < 64) s_pred4[896 + tid] = p4[896 + tid]; // 960 total
        const float4* c4 = (const float4*)(tcls + (size_t)base * 20);
        #pragma unroll
        for (int k = 0; k < 5; k++)                       // 5*128 = 640
            s_tcls4[tid + k * TPB] = c4[tid + k * TPB];
        s_tbox[tid] = ((const float4*)tbox)[base + tid];
    } else {
        float* sp = (float*)s_pred4;
        float* sc = (float*)s_tcls4;
        for (int e = tid; e < bcnt * 30; e += TPB) sp[e] = pred[(size_t)base * 30 + e];
        for (int e = tid; e < bcnt * 20; e += TPB) sc[e] = tcls[(size_t)base * 20 + e];
        if (tid < bcnt) s_tbox[tid] = ((const float4*)tbox)[base + tid];
    }

    // ---- mask dtype detection: 2KB, one uint4/thread, pure bit ops ----
    // byte>1 anywhere => f32 (4-byte). no nonzero byte at offset%4!=0 => int32 (4-byte).
    // else bool (1-byte).
    int lgt1 = 0, loff = 0;
    if (ncells >= 2048) {                 // buffer >= ncells bytes in every mode
        uint4 v = ((const uint4*)mask)[tid];
        unsigned int a = v.x | v.y | v.z | v.w;          // union of words
        if (a & 0xFEFEFEFEu) lgt1 = 1;                   // some byte > 1
        if ((v.x & 0xFFFFFF00u) | (v.y & 0xFFFFFF00u) |
            (v.z & 0xFFFFFF00u) | (v.w & 0xFFFFFF00u)) loff = 1;
    } else {
        const unsigned char* m = (const unsigned char*)mask;
        for (int i = tid; i < ncells; i += TPB) {
            unsigned char b = m[i];
            if (b > 1) lgt1 = 1;
            if ((i & 3) != 0 && b != 0) loff = 1;
        }
    }
    int gt1 = __syncthreads_or(lgt1);     // also orders the staging stores
    int off = __syncthreads_or(loff);
    const bool four_byte = (gt1 != 0) || (off == 0);

    // ---- per-cell loss: reads from smem at natural strides ----
    float scls = 0.0f, sno = 0.0f, sreg = 0.0f, sct = 0.0f;
    if (tid < bcnt) {
        const int c = base + tid;
        float fm;
        if (four_byte) fm = (((const unsigned int*)mask)[c] != 0u) ? 1.0f : 0.0f;
        else           fm = (((const unsigned char*)mask)[c] != 0)  ? 1.0f : 0.0f;

        const float2* P2 = (const float2*)s_pred4 + tid * 15;  // 8B-aligned
        const float4* C4 = s_tcls4 + tid * 5;                  // 16B-aligned
        float4 tb = s_tbox[tid];

        float2 p01 = P2[0], p23 = P2[1], p45 = P2[2], p67 = P2[3], p89 = P2[4];

        // classification loss: P[10+j] vs C[j]
        float cls = 0.0f;
        #pragma unroll
        for (int k = 0; k < 5; k++) {
            float4 cc = C4[k];
            float2 qa = P2[5 + 2 * k];
            float2 qb = P2[6 + 2 * k];
            float d0 = qa.x - cc.x, d1 = qa.y - cc.y;
            float d2 = qb.x - cc.z, d3 = qb.y - cc.w;
            cls = fmaf(d0, d0, cls);
            cls = fmaf(d1, d1, cls);
            cls = fmaf(d2, d2, cls);
            cls = fmaf(d3, d3, cls);
        }
        scls = fm * cls;

        sno = (1.0f - fm) * (p45.x * p45.x + p89.y * p89.y);   // raw; x0.5 later

        const float invS = 1.0f / (float)SGRID;
        float tx = tb.x * invS, ty = tb.y * invS;
        float t0 = tx - 0.5f * tb.z, t1 = ty - 0.5f * tb.w;
        float t2 = tx + 0.5f * tb.z, t3 = ty + 0.5f * tb.w;

        float i1 = iou_vs_t(p01.x, p01.y, p23.x, p23.y, t0, t1, t2, t3);
        float i2 = iou_vs_t(p45.y, p67.x, p67.y, p89.x, t0, t1, t2, t3);
        bool take1 = i1 > i2;
        float bx0 = take1 ? p01.x : p45.y;
        float bx1 = take1 ? p01.y : p67.x;
        float bx2 = take1 ? p23.x : p67.y;
        float bx3 = take1 ? p23.y : p89.x;
        float bx4 = take1 ? p23.y == p23.y ? (take1 ? p45.x : p89.y) : 0.0f
                          : p89.y;  // conf of best box
        bx4 = take1 ? p45.x : p89.y;
        float best_iou = take1 ? i1 : i2;

        float dx = bx0 - tb.x, dy = bx1 - tb.y;
        float xy = dx * dx + dy * dy;

        bool on = fm > 0.0f;
        float dw = sqrtf(on ? bx2 : 1.0f) - sqrtf(on ? tb.z : 1.0f);
        float dh = sqrtf(on ? bx3 : 1.0f) - sqrtf(on ? tb.w : 1.0f);
        sreg = fm * (xy + dw * dw + dh * dh);                  // raw; x5 later

        float dc = bx4 - best_iou;
        sct = fm * dc * dc;
    }

    // ---- block reduce (fp32) ----
    #pragma unroll
    for (int o = 16; o > 0; o >>= 1) {
        scls += __shfl_down_sync(0xFFFFFFFFu, scls, o);
        sno  += __shfl_down_sync(0xFFFFFFFFu, sno,  o);
        sreg += __shfl_down_sync(0xFFFFFFFFu, sreg, o);
        sct  += __shfl_down_sync(0xFFFFFFFFu, sct,  o);
    }
    int wid = tid >> 5, lid = tid & 31;
    if (lid == 0) s_red[wid] = make_float4(scls, sno, sreg, sct);
    __syncthreads();
    if (tid == 0) {
        float4 v = s_red[0];
        #pragma unroll
        for (int w = 1; w < TPB / 32; w++) {
            v.x += s_red[w].x; v.y += s_red[w].y;
            v.z += s_red[w].z; v.w += s_red[w].w;
        }
        g_part[bid] = v;
        __threadfence();
        unsigned int done = atomicAdd(&g_count, 1u);
        if (done == (unsigned int)nblocks - 1u) s_last = 1;
    }
    __syncthreads();

    // ---- last block finalizes in fp64 ----
    if (s_last) {
        double dx = 0.0, dy = 0.0, dz = 0.0, dw = 0.0;
        for (int i = tid; i < nblocks; i += TPB) {
            float4 v = g_part[i];
            dx += (double)v.x; dy += (double)v.y;
            dz += (double)v.z; dw += (double)v.w;
        }
        #pragma unroll
        for (int o = 16; o > 0; o >>= 1) {
            dx += __shfl_down_sync(0xFFFFFFFFu, dx, o);
            dy += __shfl_down_sync(0xFFFFFFFFu, dy, o);
            dz += __shfl_down_sync(0xFFFFFFFFu, dz, o);
            dw += __shfl_down_sync(0xFFFFFFFFu, dw, o);
        }
        if (lid == 0) {
            s_dred[wid][0] = dx; s_dred[wid][1] = dy;
            s_dred[wid][2] = dz; s_dred[wid][3] = dw;
        }
        __syncthreads();
        if (tid == 0) {
            double cls = 0.0, no = 0.0, reg = 0.0, ct = 0.0;
            #pragma unroll
            for (int w = 0; w < TPB / 32; w++) {
                cls += s_dred[w][0]; no += s_dred[w][1];
                reg += s_dred[w][2]; ct += s_dred[w][3];
            }
            no  *= L_NOOBJ;
            reg *= L_COORD;
            double tot = cls + no + reg + ct;
            out[0] = (float)(tot * invN);
            out[1] = (float)(reg * invN);
            out[2] = (float)(ct  * invN);
            out[3] = (float)(no  * invN);
            out[4] = (float)(cls * invN);
            g_count = 0;   // reset for next graph replay
        }
    }
}

extern "C" void kernel_launch(void* const* d_in, const int* in_sizes, int n_in,
                              void* d_out, int out_size) {
    const float* pred = (const float*)d_in[0];
    const float* tbox = (const float*)d_in[1];
    const float* tcls = (const float*)d_in[2];
    const void*  mask = d_in[3];

    int ncells = in_sizes[0] / 30;               // N*28*28
    int nbatch = ncells / (SGRID * SGRID);       // N
    double invN = 1.0 / (double)nbatch;
    int nblocks = (ncells + CELLS - 1) / CELLS;  // 6272 for N=1024

    yolo_fused<<<nblocks, TPB>>>(pred, tbox, tcls, mask, ncells, nblocks,
                                 (float*)d_out, invN);
}

// round 4
// speedup vs baseline: 1.6097x; 1.3926x over previous
#include <cuda_runtime.h>
#include <stdint.h>

// YOLO loss, single fused kernel, barrier-free structure (R1 access pattern).
// Inputs: pred (N,28,28,30) f32, target_boxes (N,28,28,4) f32,
// target_cls (N,28,28,20) f32, has_object_map (N,28,28) bool (dtype auto-detect).
// Output: 5 f32 [total, reg, contain, noobj, cls] / N.

#define SGRID 28
#define TPB   256
#define L_COORD 5.0
#define L_NOOBJ 0.5

__device__ double       g_acc[4] = {0.0, 0.0, 0.0, 0.0};  // cls, noobj, reg, contain
__device__ unsigned int g_count  = 0;

__device__ __forceinline__ float iou_vs_t(float bcx, float bcy, float bw, float bh,
                                          float t0, float t1, float t2, float t3) {
    const float invS = 1.0f / (float)SGRID;
    float bx = bcx * invS, by = bcy * invS;
    float b0 = bx - 0.5f * bw, b1 = by - 0.5f * bh;
    float b2 = bx + 0.5f * bw, b3 = by + 0.5f * bh;
    float lt0 = fmaxf(b0, t0), lt1 = fmaxf(b1, t1);
    float rb0 = fminf(b2, t2), rb1 = fminf(b3, t3);
    float w = fmaxf(rb0 - lt0, 0.0f), h = fmaxf(rb1 - lt1, 0.0f);
    float inter = w * h;
    float a1 = (b2 - b0) * (b3 - b1);
    float a2 = (t2 - t0) * (t3 - t1);
    float denom = a1 + a2 - inter;
    return inter / (denom > 0.0f ? denom : 1.0f);
}

__global__ void __launch_bounds__(TPB)
yolo_fused(const float* __restrict__ pred,
           const float* __restrict__ tbox,
           const float* __restrict__ tcls,
           const void*  __restrict__ mask,
           int ncells, int nblocks,
           float* __restrict__ out, double invN) {
    const int tid = threadIdx.x;
    const int lid = tid & 31;
    const int wid = tid >> 5;
    const int idx = blockIdx.x * TPB + tid;

    // ---- mask dtype detection: per-warp, barrier-free, 512B L2-hot scan ----
    // f32 1.0 has bytes 0x80/0x3f (>1). int32 0/1: nonzero bytes only at off%4==0.
    // 4-byte element <=> (some byte>1) || (no nonzero byte at off%4!=0).
    bool four_byte;
    {
        uint4 v = ((const uint4*)mask)[lid];          // first 512 B (mask >= 784 B)
        unsigned int a = v.x | v.y | v.z | v.w;
        int gt1 = __any_sync(0xFFFFFFFFu, (a & 0xFEFEFEFEu) != 0u);
        int off = __any_sync(0xFFFFFFFFu,
                  ((v.x | v.y | v.z | v.w) & 0xFFFFFF00u) != 0u);
        four_byte = (gt1 != 0) || (off == 0);
    }

    // ---- per-cell loss ----
    float scls = 0.0f, sno = 0.0f, sreg = 0.0f, sct = 0.0f;
    if (idx < ncells) {
        float fm;
        if (four_byte) fm = (((const unsigned int*)mask)[idx] != 0u) ? 1.0f : 0.0f;
        else           fm = (((const unsigned char*)mask)[idx] != 0)  ? 1.0f : 0.0f;

        // pred: 30 floats/cell, 8B-aligned stride -> 15 x float2
        float p[30];
        const float2* p2 = (const float2*)(pred + (size_t)idx * 30);
        #pragma unroll
        for (int i = 0; i < 15; i++) {
            float2 v = __ldg(p2 + i);
            p[2 * i] = v.x; p[2 * i + 1] = v.y;
        }
        float4 tb = __ldg((const float4*)tbox + idx);
        // tcls: 20 floats/cell, 16B-aligned -> 5 x float4
        float tc[20];
        const float4* c4 = (const float4*)(tcls + (size_t)idx * 20);
        #pragma unroll
        for (int i = 0; i < 5; i++) {
            float4 v = __ldg(c4 + i);
            tc[4 * i] = v.x; tc[4 * i + 1] = v.y;
            tc[4 * i + 2] = v.z; tc[4 * i + 3] = v.w;
        }

        float cls = 0.0f;
        #pragma unroll
        for (int j = 0; j < 20; j++) {
            float d = p[10 + j] - tc[j];
            cls = fmaf(d, d, cls);
        }
        scls = fm * cls;

        sno = (1.0f - fm) * (p[4] * p[4] + p[9] * p[9]);   // raw; x0.5 in finalize

        const float invS = 1.0f / (float)SGRID;
        float tx = tb.x * invS, ty = tb.y * invS;
        float t0 = tx - 0.5f * tb.z, t1 = ty - 0.5f * tb.w;
        float t2 = tx + 0.5f * tb.z, t3 = ty + 0.5f * tb.w;

        float i1 = iou_vs_t(p[0], p[1], p[2], p[3], t0, t1, t2, t3);
        float i2 = iou_vs_t(p[5], p[6], p[7], p[8], t0, t1, t2, t3);
        bool take1 = i1 > i2;
        float bx0 = take1 ? p[0] : p[5];
        float bx1 = take1 ? p[1] : p[6];
        float bx2 = take1 ? p[2] : p[7];
        float bx3 = take1 ? p[3] : p[8];
        float bx4 = take1 ? p[4] : p[9];
        float best_iou = take1 ? i1 : i2;

        float dx = bx0 - tb.x, dy = bx1 - tb.y;
        float xy = dx * dx + dy * dy;

        bool on = fm > 0.0f;
        float dw = sqrtf(on ? bx2 : 1.0f) - sqrtf(on ? tb.z : 1.0f);
        float dh = sqrtf(on ? bx3 : 1.0f) - sqrtf(on ? tb.w : 1.0f);
        sreg = fm * (xy + dw * dw + dh * dh);              // raw; x5 in finalize

        float dc = bx4 - best_iou;
        sct = fm * dc * dc;
    }

    // ---- block reduce (fp32 shuffles -> smem -> fp64 atomics) ----
    #pragma unroll
    for (int o = 16; o > 0; o >>= 1) {
        scls += __shfl_down_sync(0xFFFFFFFFu, scls, o);
        sno  += __shfl_down_sync(0xFFFFFFFFu, sno,  o);
        sreg += __shfl_down_sync(0xFFFFFFFFu, sreg, o);
        sct  += __shfl_down_sync(0xFFFFFFFFu, sct,  o);
    }
    __shared__ float4 s_red[TPB / 32];
    __shared__ int    s_last;
    if (tid == 0) s_last = 0;
    if (lid == 0) s_red[wid] = make_float4(scls, sno, sreg, sct);
    __syncthreads();
    if (tid == 0) {
        float4 v = s_red[0];
        #pragma unroll
        for (int w = 1; w < TPB / 32; w++) {
            v.x += s_red[w].x; v.y += s_red[w].y;
            v.z += s_red[w].z; v.w += s_red[w].w;
        }
        atomicAdd(&g_acc[0], (double)v.x);
        atomicAdd(&g_acc[1], (double)v.y);
        atomicAdd(&g_acc[2], (double)v.z);
        atomicAdd(&g_acc[3], (double)v.w);
        __threadfence();
        unsigned int done = atomicAdd(&g_count, 1u);
        if (done == (unsigned int)nblocks - 1u) s_last = 1;
    }
    __syncthreads();

    // ---- last block finalizes and resets accumulators for next replay ----
    if (s_last && tid == 0) {
        double cls = g_acc[0];
        double no  = L_NOOBJ * g_acc[1];
        double reg = L_COORD * g_acc[2];
        double ct  = g_acc[3];
        double tot = cls + no + reg + ct;
        out[0] = (float)(tot * invN);
        out[1] = (float)(reg * invN);
        out[2] = (float)(ct  * invN);
        out[3] = (float)(no  * invN);
        out[4] = (float)(cls * invN);
        g_acc[0] = 0.0; g_acc[1] = 0.0; g_acc[2] = 0.0; g_acc[3] = 0.0;
        g_count = 0;
    }
}

extern "C" void kernel_launch(void* const* d_in, const int* in_sizes, int n_in,
                              void* d_out, int out_size) {
    const float* pred = (const float*)d_in[0];
    const float* tbox = (const float*)d_in[1];
    const float* tcls = (const float*)d_in[2];
    const void*  mask = d_in[3];

    int ncells = in_sizes[0] / 30;               // N*28*28
    int nbatch = ncells / (SGRID * SGRID);       // N
    double invN = 1.0 / (double)nbatch;
    int nblocks = (ncells + TPB - 1) / TPB;      // 3136 for N=1024

    yolo_fused<<<nblocks, TPB>>>(pred, tbox, tcls, mask, ncells, nblocks,
                                 (float*)d_out, invN);
}